// round 16
// baseline (speedup 1.0000x reference)
#include <cuda_runtime.h>
#include <cstdint>

// Exact analytical collapse (bit-exact since R1): post-attention LIF can
// never spike -> pw@0=0 -> BN(0) = p_beta[c] broadcast over
// [T=4,B=2,C=128,8*32*32]. float4 index j -> c = (j>>11)&127.
//
// R12: dual-path write experiment. Measured ceilings: STG ~4.3 TB/s,
// TMA bulk ~2.3 TB/s. If the caps are per-path (SM ingress) not global
// (LTS write ports), driving both concurrently sums them.
// Planes 0..351  (11.5MB) -> TMA bulk stores (full in-kernel completion).
// Planes 352..1023 (22MB) -> STG grid-stride.

static constexpr int PLANE_FLOATS = 8192;            // 32 KB per plane
static constexpr int TMA_PLANES   = 352;
static constexpr int ALL_PLANES   = 1024;
static constexpr int THREADS      = 256;
static constexpr int STG_BLOCKS   = 832;
static constexpr int GRID         = TMA_PLANES + STG_BLOCKS;   // 1184 = 148*8
static constexpr int SMEM_FLOATS  = 4096;            // 16 KB buffer
static constexpr int STG_F4_BASE  = TMA_PLANES * (PLANE_FLOATS / 4);   // 720,896
static constexpr int STG_F4_TOTAL = (ALL_PLANES - TMA_PLANES) * (PLANE_FLOATS / 4); // 1,376,256

__global__ __launch_bounds__(THREADS)
void bisda_dualpath(const float* __restrict__ p_beta,
                    float* __restrict__ out) {
    __shared__ __align__(128) float buf[SMEM_FLOATS];

    const int b = blockIdx.x;

    if (b < TMA_PLANES) {
        // ---- TMA path: one plane per block, two 16KB bulk stores ----
        const float v = __ldg(p_beta + (b & 127));
        const float4 v4 = make_float4(v, v, v, v);
        float4* b4 = reinterpret_cast<float4*>(buf);
#pragma unroll
        for (int k = 0; k < SMEM_FLOATS / 4 / THREADS; ++k)   // 4 x STS.128
            b4[threadIdx.x + k * THREADS] = v4;
        __syncthreads();

        if (threadIdx.x == 0) {
            asm volatile("fence.proxy.async.shared::cta;" ::: "memory");
            uint32_t saddr;
            asm("{ .reg .u64 t; cvta.to.shared.u64 t, %1; cvt.u32.u64 %0, t; }"
                : "=r"(saddr) : "l"(buf));
            uint64_t g0 = (uint64_t)(out + (size_t)b * PLANE_FLOATS);
            uint64_t g1 = g0 + SMEM_FLOATS * 4;
            asm volatile("cp.async.bulk.global.shared::cta.bulk_group [%0], [%1], %2;"
                         :: "l"(g0), "r"(saddr), "n"(SMEM_FLOATS * 4) : "memory");
            asm volatile("cp.async.bulk.global.shared::cta.bulk_group [%0], [%1], %2;"
                         :: "l"(g1), "r"(saddr), "n"(SMEM_FLOATS * 4) : "memory");
            asm volatile("cp.async.bulk.commit_group;" ::: "memory");
            // Full completion wait: writes committed before kernel end, so
            // no drain leaks into the next graph replay.
            asm volatile("cp.async.bulk.wait_group 0;" ::: "memory");
        }
    } else {
        // ---- STG path: grid-stride over planes [352, 1024) ----
        const int stride = STG_BLOCKS * THREADS;
        float4* o4 = reinterpret_cast<float4*>(out);
        for (int i = (b - TMA_PLANES) * THREADS + threadIdx.x;
             i < STG_F4_TOTAL; i += stride) {
            const int j = i + STG_F4_BASE;
            const int c = (j >> 11) & 127;
            const float v = __ldg(p_beta + c);
            __stcg(o4 + j, make_float4(v, v, v, v));
        }
    }
}

extern "C" void kernel_launch(void* const* d_in, const int* in_sizes, int n_in,
                              void* d_out, int out_size) {
    const float* p_beta = (const float*)d_in[11];
    bisda_dualpath<<<GRID, THREADS>>>(p_beta, (float*)d_out);
}